// round 4
// baseline (speedup 1.0000x reference)
#include <cuda_runtime.h>
#include <math.h>

#define NE 320000
#define NA 10000
#define NAP 10240
#define CAP 128            // per-atom bin capacity (P(deg>128) ~ e^-81)
#define RCV 5.0f
#define TBL_N 2048
#define PIF 3.14159265358979323846f

// ---- scratch (device globals; no runtime allocation) ----
__device__ float g_pre[(size_t)NA * CAP * 40];  // per edge (binned): comps[35], u, sj[4]
__device__ float g_tbl[(TBL_N + 1) * 48];       // R(d)*fc(d) table
__device__ int   g_cursor[NAP];
__device__ float g_semb[12];

__device__ __forceinline__ float silu(float x) { return x / (1.0f + __expf(-x)); }

// ---- prep: table build (blocks 0..8), zero cursors (9..48), species embedding (49) ----
__global__ __launch_bounds__(256) void k_prep(
    const float* __restrict__ Ws1, const float* __restrict__ bs1,
    const float* __restrict__ Ws2, const float* __restrict__ bs2,
    const float* __restrict__ Wr1, const float* __restrict__ br1,
    const float* __restrict__ Wr2, const float* __restrict__ br2)
{
    int bid = blockIdx.x, t = threadIdx.x;
    if (bid < 9) {
        __shared__ float sW1[512];     // transposed: [64][8]
        __shared__ float sB1[64];
        __shared__ float sW2[3072];    // [64][48]
        __shared__ float sB2[48];
        for (int i = t; i < 512; i += 256) { int ii = i >> 3, k = i & 7; sW1[i] = Wr1[k * 64 + ii]; }
        for (int i = t; i < 64; i += 256) sB1[i] = br1[i];
        for (int i = t; i < 3072; i += 256) sW2[i] = Wr2[i];
        if (t < 48) sB2[t] = br2[t];
        __syncthreads();
        int idx = bid * 256 + t;
        if (idx > TBL_N) return;
        float d = idx * (RCV / TBL_N);
        float dd = fmaxf(d, 1e-6f);
        float fc = 0.5f * (cosf(PIF * d * (1.0f / RCV)) + 1.0f);
        float a1 = PIF * dd * (1.0f / RCV);
        float s1, c1;
        sincosf(a1, &s1, &c1);
        float pref = sqrtf(2.0f / RCV) / dd;
        float bes[8];
        {
            float prev = 0.0f, cur = s1, twoc = 2.0f * c1;
            bes[0] = cur * pref;
#pragma unroll
            for (int k = 1; k < 8; k++) { float nxt = twoc * cur - prev; bes[k] = nxt * pref; prev = cur; cur = nxt; }
        }
        float acc[48];
#pragma unroll
        for (int j = 0; j < 48; j++) acc[j] = sB2[j];
#pragma unroll 2
        for (int i = 0; i < 64; i++) {
            float h = sB1[i];
#pragma unroll
            for (int k = 0; k < 8; k++) h += bes[k] * sW1[i * 8 + k];
            h = silu(h);
            const float* w = &sW2[i * 48];
#pragma unroll
            for (int j = 0; j < 48; j++) acc[j] += h * w[j];
        }
        float* o = g_tbl + (size_t)idx * 48;
#pragma unroll
        for (int j = 0; j < 48; j++) o[j] = silu(acc[j]) * fc;
    } else if (bid < 49) {
        int i = (bid - 9) * 256 + t;
        if (i < NAP) g_cursor[i] = 0;
    } else {
        if (t < 3) {
            float tv[16];
#pragma unroll
            for (int i = 0; i < 16; i++) tv[i] = tanhf(Ws1[t * 16 + i] + bs1[i]);
#pragma unroll
            for (int s = 0; s < 4; s++) {
                float a = bs2[s];
#pragma unroll
                for (int i = 0; i < 16; i++) a += tv[i] * Ws2[i * 4 + s];
                g_semb[t * 4 + s] = a;
            }
        }
    }
}

// ---- pass 1: per-edge angular comps + scaled d + sj, written to per-atom bin ----
__global__ __launch_bounds__(128) void k_edge(
    const float* __restrict__ rij, const int* __restrict__ species,
    const int* __restrict__ fa, const int* __restrict__ sa)
{
    __shared__ float buf[4][40 * 33];   // per-warp transpose buffer, padded stride
    __shared__ int   sp[4][32];

    int t = threadIdx.x, warp = t >> 5, lane = t & 31;
    int e = blockIdx.x * 128 + t;

    float x = rij[3 * e + 0], y = rij[3 * e + 1], z = rij[3 * e + 2];
    float d = sqrtf(x * x + y * y + z * z + 1e-12f);
    float inv = 1.0f / d;
    float hx = x * inv, hy = y * inv, hz = z * inv;
    float u = d * ((float)TBL_N / RCV);

    int a = fa[e];
    int row = a * CAP + atomicAdd(&g_cursor[a], 1);
    sp[warp][lane] = row;

    float px2 = hx * hx, px3 = px2 * hx, px4 = px2 * px2;
    float py2 = hy * hy, py3 = py2 * hy, py4 = py2 * py2;
    float pz2 = hz * hz, pz3 = pz2 * hz, pz4 = pz2 * pz2;
    const float PX[5] = {1.f, hx, px2, px3, px4};
    const float PY[5] = {1.f, hy, py2, py3, py4};
    const float PZ[5] = {1.f, hz, pz2, pz3, pz4};
    constexpr int PA[35] = {0, 0,0,1, 0,0,0,1,1,2, 0,0,0,0,1,1,1,2,2,3, 0,0,0,0,0,1,1,1,1,2,2,2,3,3,4};
    constexpr int PB[35] = {0, 0,1,0, 0,1,2,0,1,0, 0,1,2,3,0,1,2,0,1,0, 0,1,2,3,4,0,1,2,3,0,1,2,0,1,0};
    constexpr int PC[35] = {0, 1,0,0, 2,1,0,1,0,0, 3,2,1,0,2,1,0,1,0,0, 4,3,2,1,0,3,2,1,0,2,1,0,1,0,0};
    float* bb = buf[warp];
#pragma unroll
    for (int c = 0; c < 35; c++) bb[c * 33 + lane] = PX[PA[c]] * PY[PB[c]] * PZ[PC[c]];
    bb[35 * 33 + lane] = u;
    int spc = species[sa[e]];
#pragma unroll
    for (int s = 0; s < 4; s++) bb[(36 + s) * 33 + lane] = g_semb[spc * 4 + s];
    __syncwarp();

    for (int k = lane; k < 32 * 40; k += 32) {
        int el = k / 40, j = k - el * 40;
        g_pre[(size_t)sp[warp][el] * 40 + j] = bb[j * 33 + el];
    }
}

// ---- pass 2: fused per-atom accumulation + MLP (one warp per atom) ----
__global__ __launch_bounds__(256) void k_atom_mlp(
    const float* __restrict__ Wa1, const float* __restrict__ ba1,
    const float* __restrict__ Wa2, const float* __restrict__ ba2,
    const float* __restrict__ Wa3, const float* __restrict__ ba3,
    float* __restrict__ out)
{
    __shared__ float stage[8][2][40];
    __shared__ float sfeat[8][192];
    __shared__ float sh1[8][64];
    __shared__ float sW2[4096];
    __shared__ float sW3[64], sB1[64], sB2[64];

    int t = threadIdx.x, warp = t >> 5, lane = t & 31;
    for (int i = t; i < 4096; i += 256) sW2[i] = Wa2[i];
    if (t < 64) { sW3[t] = Wa3[t]; sB1[t] = ba1[t]; sB2[t] = ba2[t]; }
    __syncthreads();

    int n = blockIdx.x * 8 + warp;           // grid is exactly NA/8
    int cnt = g_cursor[n];
    int r = lane & 7, s = lane >> 3;
    float acc[35];
#pragma unroll
    for (int c = 0; c < 35; c++) acc[c] = 0.f;
    float lin = 0.f;
    const float* base = g_pre + (size_t)n * CAP * 40;
    const float* tblr = g_tbl + r;

    float4 v = make_float4(0.f, 0.f, 0.f, 0.f);
    if (cnt > 0 && lane < 10) v = ((const float4*)base)[lane];
    float u = __shfl_sync(0xffffffffu, v.w, 8);
    float ta[6], tb[6], fr_cur;
    {
        int ir = (int)u; ir = max(0, min(ir, TBL_N - 1));
        fr_cur = u - (float)ir;
        const float* t0 = tblr + (size_t)ir * 48;
#pragma unroll
        for (int k = 0; k < 6; k++) { ta[k] = t0[8 * k]; tb[k] = t0[48 + 8 * k]; }
    }

#pragma unroll 2
    for (int i = 0; i < cnt; i++) {
        float* sb = stage[warp][i & 1];
        if (lane < 10) ((float4*)sb)[lane] = v;
        __syncwarp();
        if (i + 1 < cnt && lane < 10)
            v = ((const float4*)(base + (size_t)(i + 1) * 40))[lane];
        float u_next = __shfl_sync(0xffffffffu, v.w, 8);
        int irn = (int)u_next; irn = max(0, min(irn, TBL_N - 1));
        float fr_next = u_next - (float)irn;
        float na[6], nb[6];
        {
            const float* tn = tblr + (size_t)irn * 48;
#pragma unroll
            for (int k = 0; k < 6; k++) { na[k] = tn[8 * k]; nb[k] = tn[48 + 8 * k]; }
        }
        float F[6];
#pragma unroll
        for (int k = 0; k < 6; k++) F[k] = fmaf(fr_cur, tb[k] - ta[k], ta[k]);
        float sj = sb[36 + s];
        lin = fmaf(F[0], sj, lin);
        float m0 = F[1] * sj, m1 = F[2] * sj, m2 = F[3] * sj, m3 = F[4] * sj, m4 = F[5] * sj;
        const float4* cp = (const float4*)sb;
        float4 q0 = cp[0], q1 = cp[1], q2 = cp[2], q3 = cp[3], q4 = cp[4],
               q5 = cp[5], q6 = cp[6], q7 = cp[7], q8 = cp[8];
        acc[0]  = fmaf(m0, q0.x, acc[0]);
        acc[1]  = fmaf(m1, q0.y, acc[1]);  acc[2]  = fmaf(m1, q0.z, acc[2]);  acc[3]  = fmaf(m1, q0.w, acc[3]);
        acc[4]  = fmaf(m2, q1.x, acc[4]);  acc[5]  = fmaf(m2, q1.y, acc[5]);  acc[6]  = fmaf(m2, q1.z, acc[6]);
        acc[7]  = fmaf(m2, q1.w, acc[7]);  acc[8]  = fmaf(m2, q2.x, acc[8]);  acc[9]  = fmaf(m2, q2.y, acc[9]);
        acc[10] = fmaf(m3, q2.z, acc[10]); acc[11] = fmaf(m3, q2.w, acc[11]);
        acc[12] = fmaf(m3, q3.x, acc[12]); acc[13] = fmaf(m3, q3.y, acc[13]);
        acc[14] = fmaf(m3, q3.z, acc[14]); acc[15] = fmaf(m3, q3.w, acc[15]);
        acc[16] = fmaf(m3, q4.x, acc[16]); acc[17] = fmaf(m3, q4.y, acc[17]);
        acc[18] = fmaf(m3, q4.z, acc[18]); acc[19] = fmaf(m3, q4.w, acc[19]);
        acc[20] = fmaf(m4, q5.x, acc[20]); acc[21] = fmaf(m4, q5.y, acc[21]);
        acc[22] = fmaf(m4, q5.z, acc[22]); acc[23] = fmaf(m4, q5.w, acc[23]);
        acc[24] = fmaf(m4, q6.x, acc[24]); acc[25] = fmaf(m4, q6.y, acc[25]);
        acc[26] = fmaf(m4, q6.z, acc[26]); acc[27] = fmaf(m4, q6.w, acc[27]);
        acc[28] = fmaf(m4, q7.x, acc[28]); acc[29] = fmaf(m4, q7.y, acc[29]);
        acc[30] = fmaf(m4, q7.z, acc[30]); acc[31] = fmaf(m4, q7.w, acc[31]);
        acc[32] = fmaf(m4, q8.x, acc[32]); acc[33] = fmaf(m4, q8.y, acc[33]);
        acc[34] = fmaf(m4, q8.z, acc[34]);
        fr_cur = fr_next;
#pragma unroll
        for (int k = 0; k < 6; k++) { ta[k] = na[k]; tb[k] = nb[k]; }
    }

    // contract squared moments into feat[192] (per-warp smem)
    float* sf = sfeat[warp];
    sf[r * 4 + s] = lin;
    sf[(8 + r) * 4 + s] = acc[0] * acc[0];
    sf[(16 + r) * 4 + s] = acc[1] * acc[1] + acc[2] * acc[2] + acc[3] * acc[3];
    sf[(24 + r) * 4 + s] = acc[4] * acc[4] + 2.f * acc[5] * acc[5] + acc[6] * acc[6]
                         + 2.f * acc[7] * acc[7] + 2.f * acc[8] * acc[8] + acc[9] * acc[9];
    const float nm3[10] = {1, 3, 3, 1, 3, 6, 3, 3, 3, 1};
    float f3 = 0.f;
#pragma unroll
    for (int c = 0; c < 10; c++) f3 += nm3[c] * acc[10 + c] * acc[10 + c];
    sf[(32 + r) * 4 + s] = f3;
    const float nm4[15] = {1, 4, 6, 4, 1, 4, 12, 12, 4, 6, 12, 6, 4, 4, 1};
    float f4 = 0.f;
#pragma unroll
    for (int c = 0; c < 15; c++) f4 += nm4[c] * acc[20 + c] * acc[20 + c];
    sf[(40 + r) * 4 + s] = f4;
    __syncwarp();

    // per-warp MLP: 192 -> 64 -> 64 -> 1
    float h0 = sB1[2 * lane], h1 = sB1[2 * lane + 1];
    const float2* W1 = (const float2*)Wa1;
#pragma unroll 4
    for (int f = 0; f < 192; f++) {
        float fv = sf[f];
        float2 w = __ldg(&W1[f * 32 + lane]);
        h0 += fv * w.x; h1 += fv * w.y;
    }
    h0 = silu(h0); h1 = silu(h1);
    ((float2*)sh1[warp])[lane] = make_float2(h0, h1);
    __syncwarp();

    float g0 = sB2[2 * lane], g1 = sB2[2 * lane + 1];
    const float2* W2 = (const float2*)sW2;
#pragma unroll 4
    for (int k = 0; k < 64; k++) {
        float hv = sh1[warp][k];
        float2 w = W2[k * 32 + lane];
        g0 += hv * w.x; g1 += hv * w.y;
    }
    g0 = silu(g0); g1 = silu(g1);
    float o = g0 * sW3[2 * lane] + g1 * sW3[2 * lane + 1];
#pragma unroll
    for (int off = 16; off; off >>= 1) o += __shfl_down_sync(0xffffffffu, o, off);
    if (lane == 0) out[n] = o + ba3[0];
}

extern "C" void kernel_launch(void* const* d_in, const int* in_sizes, int n_in,
                              void* d_out, int out_size) {
    const float* rij = (const float*)d_in[0];
    const int* species = (const int*)d_in[1];
    const int* fa = (const int*)d_in[2];
    const int* sa = (const int*)d_in[3];
    const float* Ws1 = (const float*)d_in[8];
    const float* bs1 = (const float*)d_in[9];
    const float* Ws2 = (const float*)d_in[10];
    const float* bs2 = (const float*)d_in[11];
    const float* Wr1 = (const float*)d_in[4];
    const float* br1 = (const float*)d_in[5];
    const float* Wr2 = (const float*)d_in[6];
    const float* br2 = (const float*)d_in[7];
    const float* Wa1 = (const float*)d_in[12];
    const float* ba1 = (const float*)d_in[13];
    const float* Wa2 = (const float*)d_in[14];
    const float* ba2 = (const float*)d_in[15];
    const float* Wa3 = (const float*)d_in[16];
    const float* ba3 = (const float*)d_in[17];
    float* out = (float*)d_out;

    k_prep<<<50, 256>>>(Ws1, bs1, Ws2, bs2, Wr1, br1, Wr2, br2);
    k_edge<<<NE / 128, 128>>>(rij, species, fa, sa);
    k_atom_mlp<<<NA / 8, 256>>>(Wa1, ba1, Wa2, ba2, Wa3, ba3, out);
}

// round 5
// speedup vs baseline: 1.1602x; 1.1602x over previous
#include <cuda_runtime.h>
#include <math.h>

#define NE 320000
#define NA 10000
#define NAP 10240
#define CAP 128            // per-atom bin capacity (P(deg>128) ~ e^-81)
#define RCV 5.0f
#define TBL_N 2048
#define PIF 3.14159265358979323846f
#define EDGE_BLOCKS (NE / 128)     // 2500
#define TBL_BLOCKS 1025            // 2 rows per block -> 2050 >= 2049

// ---- scratch (device globals; no runtime allocation) ----
__device__ float g_pre[(size_t)NA * CAP * 40];  // per edge (binned): comps[35], u, sj[4]
__device__ float g_tbl[(TBL_N + 1) * 48];       // R(d)*fc(d) table
__device__ int   g_cursor[NAP];
__device__ float g_semb[12];

__device__ __forceinline__ float silu(float x) { return x / (1.0f + __expf(-x)); }

// ---- init: zero cursors (blocks 0..39), species embedding (40) ----
__global__ void k_init(const float* __restrict__ Ws1, const float* __restrict__ bs1,
                       const float* __restrict__ Ws2, const float* __restrict__ bs2) {
    int bid = blockIdx.x, t = threadIdx.x;
    if (bid < 40) {
        int i = bid * 256 + t;
        if (i < NAP) g_cursor[i] = 0;
    } else if (t < 3) {
        float tv[16];
#pragma unroll
        for (int i = 0; i < 16; i++) tv[i] = tanhf(Ws1[t * 16 + i] + bs1[i]);
#pragma unroll
        for (int s = 0; s < 4; s++) {
            float a = bs2[s];
#pragma unroll
            for (int i = 0; i < 16; i++) a += tv[i] * Ws2[i * 4 + s];
            g_semb[t * 4 + s] = a;
        }
    }
}

// ---- pass 1: edge blocks (0..2499) + table blocks (2500..3524) in one grid ----
__global__ __launch_bounds__(128) void k_edge_tbl(
    const float* __restrict__ rij, const int* __restrict__ species,
    const int* __restrict__ fa, const int* __restrict__ sa,
    const float* __restrict__ Wr1, const float* __restrict__ br1,
    const float* __restrict__ Wr2, const float* __restrict__ br2)
{
    int t = threadIdx.x;

    if (blockIdx.x >= EDGE_BLOCKS) {
        // ---- table build: 2 rows per block, 64 threads per row ----
        __shared__ float sh[2][64];
        int b = blockIdx.x - EDGE_BLOCKS;
        int half = t >> 6, i = t & 63;
        int idx = b * 2 + half;
        bool ok = (idx <= TBL_N);
        float fc = 0.f, h = 0.f;
        if (ok) {
            float d = idx * (RCV / TBL_N);
            float dd = fmaxf(d, 1e-6f);
            fc = 0.5f * (cosf(PIF * d * (1.0f / RCV)) + 1.0f);
            float a1 = PIF * dd * (1.0f / RCV);
            float s1, c1;
            sincosf(a1, &s1, &c1);
            float pref = sqrtf(2.0f / RCV) / dd;
            float bes[8];
            float prev = 0.0f, cur = s1, twoc = 2.0f * c1;
            bes[0] = cur * pref;
#pragma unroll
            for (int k = 1; k < 8; k++) { float nxt = twoc * cur - prev; bes[k] = nxt * pref; prev = cur; cur = nxt; }
            h = br1[i];
#pragma unroll
            for (int k = 0; k < 8; k++) h = fmaf(bes[k], __ldg(&Wr1[k * 64 + i]), h);
            h = silu(h);
        }
        sh[half][i] = h;
        __syncthreads();
        if (ok && i < 48) {
            float acc = br2[i];
            const float* hh = sh[half];
#pragma unroll 8
            for (int k = 0; k < 64; k++) acc = fmaf(hh[k], __ldg(&Wr2[k * 48 + i]), acc);
            g_tbl[(size_t)idx * 48 + i] = silu(acc) * fc;
        }
        return;
    }

    // ---- edge path ----
    __shared__ float buf[4][40 * 33];   // per-warp transpose buffer, padded stride
    __shared__ int   sp[4][32];

    int warp = t >> 5, lane = t & 31;
    int e = blockIdx.x * 128 + t;

    float x = rij[3 * e + 0], y = rij[3 * e + 1], z = rij[3 * e + 2];
    float d = sqrtf(x * x + y * y + z * z + 1e-12f);
    float inv = 1.0f / d;
    float hx = x * inv, hy = y * inv, hz = z * inv;
    float u = d * ((float)TBL_N / RCV);

    int a = fa[e];
    int row = a * CAP + atomicAdd(&g_cursor[a], 1);
    sp[warp][lane] = row;

    float px2 = hx * hx, px3 = px2 * hx, px4 = px2 * px2;
    float py2 = hy * hy, py3 = py2 * hy, py4 = py2 * py2;
    float pz2 = hz * hz, pz3 = pz2 * hz, pz4 = pz2 * pz2;
    const float PX[5] = {1.f, hx, px2, px3, px4};
    const float PY[5] = {1.f, hy, py2, py3, py4};
    const float PZ[5] = {1.f, hz, pz2, pz3, pz4};
    constexpr int PA[35] = {0, 0,0,1, 0,0,0,1,1,2, 0,0,0,0,1,1,1,2,2,3, 0,0,0,0,0,1,1,1,1,2,2,2,3,3,4};
    constexpr int PB[35] = {0, 0,1,0, 0,1,2,0,1,0, 0,1,2,3,0,1,2,0,1,0, 0,1,2,3,4,0,1,2,3,0,1,2,0,1,0};
    constexpr int PC[35] = {0, 1,0,0, 2,1,0,1,0,0, 3,2,1,0,2,1,0,1,0,0, 4,3,2,1,0,3,2,1,0,2,1,0,1,0,0};
    float* bb = buf[warp];
#pragma unroll
    for (int c = 0; c < 35; c++) bb[c * 33 + lane] = PX[PA[c]] * PY[PB[c]] * PZ[PC[c]];
    bb[35 * 33 + lane] = u;
    int spc = species[sa[e]];
#pragma unroll
    for (int s = 0; s < 4; s++) bb[(36 + s) * 33 + lane] = g_semb[spc * 4 + s];
    __syncwarp();

    for (int k = lane; k < 32 * 40; k += 32) {
        int el = k / 40, j = k - el * 40;
        g_pre[(size_t)sp[warp][el] * 40 + j] = bb[j * 33 + el];
    }
}

// ---- pass 2: fused per-atom accumulation + MLP (one warp per atom) ----
__global__ __launch_bounds__(256) void k_atom_mlp(
    const float* __restrict__ Wa1, const float* __restrict__ ba1,
    const float* __restrict__ Wa2, const float* __restrict__ ba2,
    const float* __restrict__ Wa3, const float* __restrict__ ba3,
    float* __restrict__ out)
{
    __shared__ float stage[8][2][40];
    __shared__ float sfeat[8][192];
    __shared__ float sh1[8][64];
    __shared__ float sW2[4096];
    __shared__ float sW3[64], sB1[64], sB2[64];

    int t = threadIdx.x, warp = t >> 5, lane = t & 31;
    for (int i = t; i < 4096; i += 256) sW2[i] = Wa2[i];
    if (t < 64) { sW3[t] = Wa3[t]; sB1[t] = ba1[t]; sB2[t] = ba2[t]; }
    __syncthreads();

    int n = blockIdx.x * 8 + warp;           // grid is exactly NA/8
    int cnt = g_cursor[n];
    int r = lane & 7, s = lane >> 3;
    float acc[35];
#pragma unroll
    for (int c = 0; c < 35; c++) acc[c] = 0.f;
    float lin = 0.f;
    const float* base = g_pre + (size_t)n * CAP * 40;
    const float* tblr = g_tbl + r;

    float4 v = make_float4(0.f, 0.f, 0.f, 0.f);
    if (cnt > 0 && lane < 10) v = ((const float4*)base)[lane];
    float u = __shfl_sync(0xffffffffu, v.w, 8);
    float ta[6], tb[6], fr_cur;
    {
        int ir = (int)u; ir = max(0, min(ir, TBL_N - 1));
        fr_cur = u - (float)ir;
        const float* t0 = tblr + (size_t)ir * 48;
#pragma unroll
        for (int k = 0; k < 6; k++) { ta[k] = t0[8 * k]; tb[k] = t0[48 + 8 * k]; }
    }

#pragma unroll 2
    for (int i = 0; i < cnt; i++) {
        float* sb = stage[warp][i & 1];
        if (lane < 10) ((float4*)sb)[lane] = v;
        __syncwarp();
        if (i + 1 < cnt && lane < 10)
            v = ((const float4*)(base + (size_t)(i + 1) * 40))[lane];
        float u_next = __shfl_sync(0xffffffffu, v.w, 8);
        int irn = (int)u_next; irn = max(0, min(irn, TBL_N - 1));
        float fr_next = u_next - (float)irn;
        float na[6], nb[6];
        {
            const float* tn = tblr + (size_t)irn * 48;
#pragma unroll
            for (int k = 0; k < 6; k++) { na[k] = tn[8 * k]; nb[k] = tn[48 + 8 * k]; }
        }
        float F[6];
#pragma unroll
        for (int k = 0; k < 6; k++) F[k] = fmaf(fr_cur, tb[k] - ta[k], ta[k]);
        float sj = sb[36 + s];
        lin = fmaf(F[0], sj, lin);
        float m0 = F[1] * sj, m1 = F[2] * sj, m2 = F[3] * sj, m3 = F[4] * sj, m4 = F[5] * sj;
        const float4* cp = (const float4*)sb;
        float4 q0 = cp[0], q1 = cp[1], q2 = cp[2], q3 = cp[3], q4 = cp[4],
               q5 = cp[5], q6 = cp[6], q7 = cp[7], q8 = cp[8];
        acc[0]  = fmaf(m0, q0.x, acc[0]);
        acc[1]  = fmaf(m1, q0.y, acc[1]);  acc[2]  = fmaf(m1, q0.z, acc[2]);  acc[3]  = fmaf(m1, q0.w, acc[3]);
        acc[4]  = fmaf(m2, q1.x, acc[4]);  acc[5]  = fmaf(m2, q1.y, acc[5]);  acc[6]  = fmaf(m2, q1.z, acc[6]);
        acc[7]  = fmaf(m2, q1.w, acc[7]);  acc[8]  = fmaf(m2, q2.x, acc[8]);  acc[9]  = fmaf(m2, q2.y, acc[9]);
        acc[10] = fmaf(m3, q2.z, acc[10]); acc[11] = fmaf(m3, q2.w, acc[11]);
        acc[12] = fmaf(m3, q3.x, acc[12]); acc[13] = fmaf(m3, q3.y, acc[13]);
        acc[14] = fmaf(m3, q3.z, acc[14]); acc[15] = fmaf(m3, q3.w, acc[15]);
        acc[16] = fmaf(m3, q4.x, acc[16]); acc[17] = fmaf(m3, q4.y, acc[17]);
        acc[18] = fmaf(m3, q4.z, acc[18]); acc[19] = fmaf(m3, q4.w, acc[19]);
        acc[20] = fmaf(m4, q5.x, acc[20]); acc[21] = fmaf(m4, q5.y, acc[21]);
        acc[22] = fmaf(m4, q5.z, acc[22]); acc[23] = fmaf(m4, q5.w, acc[23]);
        acc[24] = fmaf(m4, q6.x, acc[24]); acc[25] = fmaf(m4, q6.y, acc[25]);
        acc[26] = fmaf(m4, q6.z, acc[26]); acc[27] = fmaf(m4, q6.w, acc[27]);
        acc[28] = fmaf(m4, q7.x, acc[28]); acc[29] = fmaf(m4, q7.y, acc[29]);
        acc[30] = fmaf(m4, q7.z, acc[30]); acc[31] = fmaf(m4, q7.w, acc[31]);
        acc[32] = fmaf(m4, q8.x, acc[32]); acc[33] = fmaf(m4, q8.y, acc[33]);
        acc[34] = fmaf(m4, q8.z, acc[34]);
        fr_cur = fr_next;
#pragma unroll
        for (int k = 0; k < 6; k++) { ta[k] = na[k]; tb[k] = nb[k]; }
    }

    // contract squared moments into feat[192] (per-warp smem)
    float* sf = sfeat[warp];
    sf[r * 4 + s] = lin;
    sf[(8 + r) * 4 + s] = acc[0] * acc[0];
    sf[(16 + r) * 4 + s] = acc[1] * acc[1] + acc[2] * acc[2] + acc[3] * acc[3];
    sf[(24 + r) * 4 + s] = acc[4] * acc[4] + 2.f * acc[5] * acc[5] + acc[6] * acc[6]
                         + 2.f * acc[7] * acc[7] + 2.f * acc[8] * acc[8] + acc[9] * acc[9];
    const float nm3[10] = {1, 3, 3, 1, 3, 6, 3, 3, 3, 1};
    float f3 = 0.f;
#pragma unroll
    for (int c = 0; c < 10; c++) f3 += nm3[c] * acc[10 + c] * acc[10 + c];
    sf[(32 + r) * 4 + s] = f3;
    const float nm4[15] = {1, 4, 6, 4, 1, 4, 12, 12, 4, 6, 12, 6, 4, 4, 1};
    float f4 = 0.f;
#pragma unroll
    for (int c = 0; c < 15; c++) f4 += nm4[c] * acc[20 + c] * acc[20 + c];
    sf[(40 + r) * 4 + s] = f4;
    __syncwarp();

    // per-warp MLP: 192 -> 64 -> 64 -> 1
    float h0 = sB1[2 * lane], h1 = sB1[2 * lane + 1];
    const float2* W1 = (const float2*)Wa1;
#pragma unroll 4
    for (int f = 0; f < 192; f++) {
        float fv = sf[f];
        float2 w = __ldg(&W1[f * 32 + lane]);
        h0 += fv * w.x; h1 += fv * w.y;
    }
    h0 = silu(h0); h1 = silu(h1);
    ((float2*)sh1[warp])[lane] = make_float2(h0, h1);
    __syncwarp();

    float g0 = sB2[2 * lane], g1 = sB2[2 * lane + 1];
    const float2* W2 = (const float2*)sW2;
#pragma unroll 4
    for (int k = 0; k < 64; k++) {
        float hv = sh1[warp][k];
        float2 w = W2[k * 32 + lane];
        g0 += hv * w.x; g1 += hv * w.y;
    }
    g0 = silu(g0); g1 = silu(g1);
    float o = g0 * sW3[2 * lane] + g1 * sW3[2 * lane + 1];
#pragma unroll
    for (int off = 16; off; off >>= 1) o += __shfl_down_sync(0xffffffffu, o, off);
    if (lane == 0) out[n] = o + ba3[0];
}

extern "C" void kernel_launch(void* const* d_in, const int* in_sizes, int n_in,
                              void* d_out, int out_size) {
    const float* rij = (const float*)d_in[0];
    const int* species = (const int*)d_in[1];
    const int* fa = (const int*)d_in[2];
    const int* sa = (const int*)d_in[3];
    const float* Wr1 = (const float*)d_in[4];
    const float* br1 = (const float*)d_in[5];
    const float* Wr2 = (const float*)d_in[6];
    const float* br2 = (const float*)d_in[7];
    const float* Ws1 = (const float*)d_in[8];
    const float* bs1 = (const float*)d_in[9];
    const float* Ws2 = (const float*)d_in[10];
    const float* bs2 = (const float*)d_in[11];
    const float* Wa1 = (const float*)d_in[12];
    const float* ba1 = (const float*)d_in[13];
    const float* Wa2 = (const float*)d_in[14];
    const float* ba2 = (const float*)d_in[15];
    const float* Wa3 = (const float*)d_in[16];
    const float* ba3 = (const float*)d_in[17];
    float* out = (float*)d_out;

    k_init<<<41, 256>>>(Ws1, bs1, Ws2, bs2);
    k_edge_tbl<<<EDGE_BLOCKS + TBL_BLOCKS, 128>>>(rij, species, fa, sa, Wr1, br1, Wr2, br2);
    k_atom_mlp<<<NA / 8, 256>>>(Wa1, ba1, Wa2, ba2, Wa3, ba3, out);
}

// round 7
// speedup vs baseline: 1.4260x; 1.2291x over previous
#include <cuda_runtime.h>
#include <stdint.h>
#include <math.h>

#define NE 320000
#define NA 10000
#define NAP 10240
#define CAP 128            // per-atom bin capacity (P(deg>128) ~ e^-81)
#define RCV 5.0f
#define TBL_N 2048
#define PIF 3.14159265358979323846f
#define EDGE_BLOCKS (NE / 128)     // 2500
#define TBL_BLOCKS 1025            // 2 rows per block -> 2050 >= 2049

// ---- scratch (device globals; no runtime allocation) ----
__device__ float g_pre[(size_t)NA * CAP * 40];  // per edge (binned): comps[35], u, sj[4]
__device__ float g_tbl[(TBL_N + 1) * 48];       // R(d)*fc(d) table
__device__ int   g_cursor[NAP];
__device__ float g_semb[12];

__device__ __forceinline__ float silu(float x) { return x / (1.0f + __expf(-x)); }

__device__ __forceinline__ void cp16(unsigned int s, const void* g) {
    asm volatile("cp.async.cg.shared.global [%0], [%1], 16;" :: "r"(s), "l"(g));
}
#define CP_COMMIT() asm volatile("cp.async.commit_group;")
#define CP_WAIT(n)  asm volatile("cp.async.wait_group %0;" :: "n"(n))

// ---- init: zero cursors (blocks 0..39), species embedding (40) ----
__global__ void k_init(const float* __restrict__ Ws1, const float* __restrict__ bs1,
                       const float* __restrict__ Ws2, const float* __restrict__ bs2) {
    int bid = blockIdx.x, t = threadIdx.x;
    if (bid < 40) {
        int i = bid * 256 + t;
        if (i < NAP) g_cursor[i] = 0;
    } else if (t < 3) {
        float tv[16];
#pragma unroll
        for (int i = 0; i < 16; i++) tv[i] = tanhf(Ws1[t * 16 + i] + bs1[i]);
#pragma unroll
        for (int s = 0; s < 4; s++) {
            float a = bs2[s];
#pragma unroll
            for (int i = 0; i < 16; i++) a += tv[i] * Ws2[i * 4 + s];
            g_semb[t * 4 + s] = a;
        }
    }
}

// ---- pass 1: edge blocks (0..2499) + table blocks (2500..3524) in one grid ----
__global__ __launch_bounds__(128) void k_edge_tbl(
    const float* __restrict__ rij, const int* __restrict__ species,
    const int* __restrict__ fa, const int* __restrict__ sa,
    const float* __restrict__ Wr1, const float* __restrict__ br1,
    const float* __restrict__ Wr2, const float* __restrict__ br2)
{
    int t = threadIdx.x;

    if (blockIdx.x >= EDGE_BLOCKS) {
        // ---- table build: 2 rows per block, 64 threads per row ----
        __shared__ float sh[2][64];
        int b = blockIdx.x - EDGE_BLOCKS;
        int half = t >> 6, i = t & 63;
        int idx = b * 2 + half;
        bool ok = (idx <= TBL_N);
        float fc = 0.f, h = 0.f;
        if (ok) {
            float d = idx * (RCV / TBL_N);
            float dd = fmaxf(d, 1e-6f);
            fc = 0.5f * (cosf(PIF * d * (1.0f / RCV)) + 1.0f);
            float a1 = PIF * dd * (1.0f / RCV);
            float s1, c1;
            sincosf(a1, &s1, &c1);
            float pref = sqrtf(2.0f / RCV) / dd;
            float bes[8];
            float prev = 0.0f, cur = s1, twoc = 2.0f * c1;
            bes[0] = cur * pref;
#pragma unroll
            for (int k = 1; k < 8; k++) { float nxt = twoc * cur - prev; bes[k] = nxt * pref; prev = cur; cur = nxt; }
            h = br1[i];
#pragma unroll
            for (int k = 0; k < 8; k++) h = fmaf(bes[k], __ldg(&Wr1[k * 64 + i]), h);
            h = silu(h);
        }
        sh[half][i] = h;
        __syncthreads();
        if (ok && i < 48) {
            float acc = br2[i];
            const float* hh = sh[half];
#pragma unroll 8
            for (int k = 0; k < 64; k++) acc = fmaf(hh[k], __ldg(&Wr2[k * 48 + i]), acc);
            g_tbl[(size_t)idx * 48 + i] = silu(acc) * fc;
        }
        return;
    }

    // ---- edge path ----
    __shared__ float buf[4][40 * 33];   // per-warp transpose buffer, padded stride
    __shared__ int   sp[4][32];

    int warp = t >> 5, lane = t & 31;
    int e = blockIdx.x * 128 + t;

    float x = rij[3 * e + 0], y = rij[3 * e + 1], z = rij[3 * e + 2];
    float d = sqrtf(x * x + y * y + z * z + 1e-12f);
    float inv = 1.0f / d;
    float hx = x * inv, hy = y * inv, hz = z * inv;
    float u = d * ((float)TBL_N / RCV);

    int a = fa[e];
    int row = a * CAP + atomicAdd(&g_cursor[a], 1);
    sp[warp][lane] = row;

    float px2 = hx * hx, px3 = px2 * hx, px4 = px2 * px2;
    float py2 = hy * hy, py3 = py2 * hy, py4 = py2 * py2;
    float pz2 = hz * hz, pz3 = pz2 * hz, pz4 = pz2 * pz2;
    const float PX[5] = {1.f, hx, px2, px3, px4};
    const float PY[5] = {1.f, hy, py2, py3, py4};
    const float PZ[5] = {1.f, hz, pz2, pz3, pz4};
    constexpr int PA[35] = {0, 0,0,1, 0,0,0,1,1,2, 0,0,0,0,1,1,1,2,2,3, 0,0,0,0,0,1,1,1,1,2,2,2,3,3,4};
    constexpr int PB[35] = {0, 0,1,0, 0,1,2,0,1,0, 0,1,2,3,0,1,2,0,1,0, 0,1,2,3,4,0,1,2,3,0,1,2,0,1,0};
    constexpr int PC[35] = {0, 1,0,0, 2,1,0,1,0,0, 3,2,1,0,2,1,0,1,0,0, 4,3,2,1,0,3,2,1,0,2,1,0,1,0,0};
    float* bb = buf[warp];
#pragma unroll
    for (int c = 0; c < 35; c++) bb[c * 33 + lane] = PX[PA[c]] * PY[PB[c]] * PZ[PC[c]];
    bb[35 * 33 + lane] = u;
    int spc = species[sa[e]];
#pragma unroll
    for (int s = 0; s < 4; s++) bb[(36 + s) * 33 + lane] = g_semb[spc * 4 + s];
    __syncwarp();

    for (int k = lane; k < 32 * 40; k += 32) {
        int el = k / 40, j = k - el * 40;
        g_pre[(size_t)sp[warp][el] * 40 + j] = bb[j * 33 + el];
    }
}

// ---- pass 2: fused per-atom accumulation + MLP; cp.async depth-4 ring ----
__global__ __launch_bounds__(256) void k_atom_mlp(
    const float* __restrict__ Wa1, const float* __restrict__ ba1,
    const float* __restrict__ Wa2, const float* __restrict__ ba2,
    const float* __restrict__ Wa3, const float* __restrict__ ba3,
    float* __restrict__ out)
{
    const int D = 4;
    __shared__ __align__(16) float stage[8][D][40];
    __shared__ float sfeat[8][192];
    __shared__ float sh1[8][64];
    __shared__ float sW2[4096];
    __shared__ float sW3[64], sB1[64], sB2[64];

    int t = threadIdx.x, warp = t >> 5, lane = t & 31;
    for (int i = t; i < 4096; i += 256) sW2[i] = Wa2[i];
    if (t < 64) { sW3[t] = Wa3[t]; sB1[t] = ba1[t]; sB2[t] = ba2[t]; }
    __syncthreads();

    int n = blockIdx.x * 8 + warp;           // grid is exactly NA/8
    int cnt = g_cursor[n];
    int r = lane & 7, s = lane >> 3;
    float acc[35];
#pragma unroll
    for (int c = 0; c < 35; c++) acc[c] = 0.f;
    float lin = 0.f;
    const float* base = g_pre + (size_t)n * CAP * 40;
    const float* tblr = g_tbl + r;
    unsigned int sbase = (unsigned int)__cvta_generic_to_shared(&stage[warp][0][0]) + lane * 16;

    // prologue: always commit exactly D groups (empty groups pad when cnt < D)
#pragma unroll
    for (int j = 0; j < D; j++) {
        if (j < cnt && lane < 10) cp16(sbase + j * 160, base + (size_t)j * 40 + lane * 4);
        CP_COMMIT();
    }

    float ta[6], tb[6], fr_cur = 0.f;
    if (cnt > 0) {
        CP_WAIT(2);
        __syncwarp();
        float u0 = stage[warp][0][35];
        int ir = (int)u0; ir = max(0, min(ir, TBL_N - 1));
        fr_cur = u0 - (float)ir;
        const float* t0 = tblr + (size_t)ir * 48;
#pragma unroll
        for (int k = 0; k < 6; k++) { ta[k] = t0[8 * k]; tb[k] = t0[48 + 8 * k]; }
    }

    for (int i = 0; i < cnt; i++) {
        CP_WAIT(2);                       // edges i and i+1 resident
        __syncwarp();
        const float* sb  = stage[warp][i & (D - 1)];
        const float* sb1 = stage[warp][(i + 1) & (D - 1)];
        float u_next = (i + 1 < cnt) ? sb1[35] : 0.f;
        int irn = (int)u_next; irn = max(0, min(irn, TBL_N - 1));
        float fr_next = u_next - (float)irn;
        float na[6], nb[6];
        {
            const float* tn = tblr + (size_t)irn * 48;
#pragma unroll
            for (int k = 0; k < 6; k++) { na[k] = tn[8 * k]; nb[k] = tn[48 + 8 * k]; }
        }
        float F[6];
#pragma unroll
        for (int k = 0; k < 6; k++) F[k] = fmaf(fr_cur, tb[k] - ta[k], ta[k]);
        float sj = sb[36 + s];
        lin = fmaf(F[0], sj, lin);
        float m0 = F[1] * sj, m1 = F[2] * sj, m2 = F[3] * sj, m3 = F[4] * sj, m4 = F[5] * sj;
        const float4* cp = (const float4*)sb;
        float4 q0 = cp[0], q1 = cp[1], q2 = cp[2], q3 = cp[3], q4 = cp[4],
               q5 = cp[5], q6 = cp[6], q7 = cp[7], q8 = cp[8];
        acc[0]  = fmaf(m0, q0.x, acc[0]);
        acc[1]  = fmaf(m1, q0.y, acc[1]);  acc[2]  = fmaf(m1, q0.z, acc[2]);  acc[3]  = fmaf(m1, q0.w, acc[3]);
        acc[4]  = fmaf(m2, q1.x, acc[4]);  acc[5]  = fmaf(m2, q1.y, acc[5]);  acc[6]  = fmaf(m2, q1.z, acc[6]);
        acc[7]  = fmaf(m2, q1.w, acc[7]);  acc[8]  = fmaf(m2, q2.x, acc[8]);  acc[9]  = fmaf(m2, q2.y, acc[9]);
        acc[10] = fmaf(m3, q2.z, acc[10]); acc[11] = fmaf(m3, q2.w, acc[11]);
        acc[12] = fmaf(m3, q3.x, acc[12]); acc[13] = fmaf(m3, q3.y, acc[13]);
        acc[14] = fmaf(m3, q3.z, acc[14]); acc[15] = fmaf(m3, q3.w, acc[15]);
        acc[16] = fmaf(m3, q4.x, acc[16]); acc[17] = fmaf(m3, q4.y, acc[17]);
        acc[18] = fmaf(m3, q4.z, acc[18]); acc[19] = fmaf(m3, q4.w, acc[19]);
        acc[20] = fmaf(m4, q5.x, acc[20]); acc[21] = fmaf(m4, q5.y, acc[21]);
        acc[22] = fmaf(m4, q5.z, acc[22]); acc[23] = fmaf(m4, q5.w, acc[23]);
        acc[24] = fmaf(m4, q6.x, acc[24]); acc[25] = fmaf(m4, q6.y, acc[25]);
        acc[26] = fmaf(m4, q6.z, acc[26]); acc[27] = fmaf(m4, q6.w, acc[27]);
        acc[28] = fmaf(m4, q7.x, acc[28]); acc[29] = fmaf(m4, q7.y, acc[29]);
        acc[30] = fmaf(m4, q7.z, acc[30]); acc[31] = fmaf(m4, q7.w, acc[31]);
        acc[32] = fmaf(m4, q8.x, acc[32]); acc[33] = fmaf(m4, q8.y, acc[33]);
        acc[34] = fmaf(m4, q8.z, acc[34]);
        __syncwarp();                      // all lanes done reading slot i before refill
        if (i + D < cnt && lane < 10)
            cp16(sbase + (i & (D - 1)) * 160, base + (size_t)(i + D) * 40 + lane * 4);
        CP_COMMIT();
        fr_cur = fr_next;
#pragma unroll
        for (int k = 0; k < 6; k++) { ta[k] = na[k]; tb[k] = nb[k]; }
    }
    CP_WAIT(0);

    // contract squared moments into feat[192] (per-warp smem)
    float* sf = sfeat[warp];
    sf[r * 4 + s] = lin;
    sf[(8 + r) * 4 + s] = acc[0] * acc[0];
    sf[(16 + r) * 4 + s] = acc[1] * acc[1] + acc[2] * acc[2] + acc[3] * acc[3];
    sf[(24 + r) * 4 + s] = acc[4] * acc[4] + 2.f * acc[5] * acc[5] + acc[6] * acc[6]
                         + 2.f * acc[7] * acc[7] + 2.f * acc[8] * acc[8] + acc[9] * acc[9];
    const float nm3[10] = {1, 3, 3, 1, 3, 6, 3, 3, 3, 1};
    float f3 = 0.f;
#pragma unroll
    for (int c = 0; c < 10; c++) f3 += nm3[c] * acc[10 + c] * acc[10 + c];
    sf[(32 + r) * 4 + s] = f3;
    const float nm4[15] = {1, 4, 6, 4, 1, 4, 12, 12, 4, 6, 12, 6, 4, 4, 1};
    float f4 = 0.f;
#pragma unroll
    for (int c = 0; c < 15; c++) f4 += nm4[c] * acc[20 + c] * acc[20 + c];
    sf[(40 + r) * 4 + s] = f4;
    __syncwarp();

    // per-warp MLP: 192 -> 64 -> 64 -> 1
    float h0 = sB1[2 * lane], h1 = sB1[2 * lane + 1];
    const float2* W1 = (const float2*)Wa1;
#pragma unroll 4
    for (int f = 0; f < 192; f++) {
        float fv = sf[f];
        float2 w = __ldg(&W1[f * 32 + lane]);
        h0 += fv * w.x; h1 += fv * w.y;
    }
    h0 = silu(h0); h1 = silu(h1);
    ((float2*)sh1[warp])[lane] = make_float2(h0, h1);
    __syncwarp();

    float g0 = sB2[2 * lane], g1 = sB2[2 * lane + 1];
    const float2* W2 = (const float2*)sW2;
#pragma unroll 4
    for (int k = 0; k < 64; k++) {
        float hv = sh1[warp][k];
        float2 w = W2[k * 32 + lane];
        g0 += hv * w.x; g1 += hv * w.y;
    }
    g0 = silu(g0); g1 = silu(g1);
    float o = g0 * sW3[2 * lane] + g1 * sW3[2 * lane + 1];
#pragma unroll
    for (int off = 16; off; off >>= 1) o += __shfl_down_sync(0xffffffffu, o, off);
    if (lane == 0) out[n] = o + ba3[0];
}

extern "C" void kernel_launch(void* const* d_in, const int* in_sizes, int n_in,
                              void* d_out, int out_size) {
    const float* rij = (const float*)d_in[0];
    const int* species = (const int*)d_in[1];
    const int* fa = (const int*)d_in[2];
    const int* sa = (const int*)d_in[3];
    const float* Wr1 = (const float*)d_in[4];
    const float* br1 = (const float*)d_in[5];
    const float* Wr2 = (const float*)d_in[6];
    const float* br2 = (const float*)d_in[7];
    const float* Ws1 = (const float*)d_in[8];
    const float* bs1 = (const float*)d_in[9];
    const float* Ws2 = (const float*)d_in[10];
    const float* bs2 = (const float*)d_in[11];
    const float* Wa1 = (const float*)d_in[12];
    const float* ba1 = (const float*)d_in[13];
    const float* Wa2 = (const float*)d_in[14];
    const float* ba2 = (const float*)d_in[15];
    const float* Wa3 = (const float*)d_in[16];
    const float* ba3 = (const float*)d_in[17];
    float* out = (float*)d_out;

    k_init<<<41, 256>>>(Ws1, bs1, Ws2, bs2);
    k_edge_tbl<<<EDGE_BLOCKS + TBL_BLOCKS, 128>>>(rij, species, fa, sa, Wr1, br1, Wr2, br2);
    k_atom_mlp<<<NA / 8, 256>>>(Wa1, ba1, Wa2, ba2, Wa3, ba3, out);
}